// round 15
// baseline (speedup 1.0000x reference)
#include <cuda_runtime.h>
#include <cuda_fp16.h>
#include <cstdint>

// Fused sparsemax(BN(x @ W + b)) via warp-level mma.sync.
// R14 = R13 + (1) 4-row interleaved epilogue (independent shuffle chains,
// joint Michelot early-exit), (2) BN shift applied at staging write,
// (3) LDSM hoist before MMA block. fp16 1-pass (x fp16, W fp16 BN-folded,
// rel_err 7.6e-4 measured), cp.async.bulk W DMA (pre-swizzled), 3-stage
// pipeline, BM=32 / 256 threads / 2 CTAs/SM.

#define FDIM 512
#define BM 32
#define THREADS 256
#define NSTAGE_IT 16                       // 16 iterations x 32 k each
#define BN_EPS 1e-5f
#define STG_STRIDE 520                     // 512 + 8 pad floats

// ---- device scratch (static, no allocation) ----
// g_WT holds W pre-swizzled: byte (k,n) -> (k>>4)*16384 + TOFF(n,(k&15)>>3) + (k&7)*2
__device__ __align__(128) __half g_WT[FDIM * FDIM];

// ---- smem: 3 stages of 34 KB + mbarriers; epilogue region unions stages ----
#define STAGE_BYTES 34816
#define A_O 0                               // 2 ksteps x 1024 = 2048
#define B_O 2048                            // 2 ksteps x 16384 (contiguous 32KB)
#define MBAR_O (3 * STAGE_BYTES)            // 104448: 3 x 8B mbarriers
#define SMEM_BYTES (MBAR_O + 64)            // 104512 (>= 32*520*4 = 66560)

// 16B-chunk swizzle inside a [rows][16 fp16] tile (8-row ldmatrix phase
// hits 8 distinct 16B slots of a 128B line).
#define TOFF(r, c) (((((r) << 1) | (c)) ^ (((r) >> 2) & 1)) << 4)

__device__ __forceinline__ uint32_t smem_u32(const void* p) {
    uint32_t a;
    asm("{ .reg .u64 t; cvta.to.shared.u64 t, %1; cvt.u32.u64 %0, t; }" : "=r"(a) : "l"(p));
    return a;
}

#define LDSM4(R, addr)                                                        \
    asm volatile("ldmatrix.sync.aligned.m8n8.x4.shared.b16 {%0,%1,%2,%3}, [%4];" \
                 : "=r"((R)[0]), "=r"((R)[1]), "=r"((R)[2]), "=r"((R)[3])     \
                 : "r"(addr))

#define MMA16816(d, a, b0, b1)                                                \
    asm volatile("mma.sync.aligned.m16n8k16.row.col.f32.f16.f16.f32 "         \
                 "{%0,%1,%2,%3},{%4,%5,%6,%7},{%8,%9},{%0,%1,%2,%3};"         \
                 : "+f"((d)[0]), "+f"((d)[1]), "+f"((d)[2]), "+f"((d)[3])     \
                 : "r"((a)[0]), "r"((a)[1]), "r"((a)[2]), "r"((a)[3]),        \
                   "r"(b0), "r"(b1))

#define MBARRIER_INIT(mb, c) \
    asm volatile("mbarrier.init.shared.b64 [%0], %1;" :: "r"((uint32_t)(mb)), "r"((uint32_t)(c)) : "memory")
#define MBARRIER_EXPECT_TX(mb, bytes) \
    asm volatile("mbarrier.arrive.expect_tx.shared.b64 _, [%0], %1;" \
                 :: "r"((uint32_t)(mb)), "r"((uint32_t)(bytes)) : "memory")
#define BULK_G2S(dst, src, size, mb)                                          \
    asm volatile("cp.async.bulk.shared::cta.global.mbarrier::complete_tx::bytes " \
                 "[%0], [%1], %2, [%3];"                                      \
                 :: "r"((uint32_t)(dst)), "l"(src), "r"((uint32_t)(size)),    \
                    "r"((uint32_t)(mb)) : "memory")
#define MBARRIER_WAIT_PARITY(mb, par) do {                                    \
    uint32_t _mb = (uint32_t)(mb), _pa = (uint32_t)(par), _dn;                \
    asm volatile("{\n\t.reg .pred p;\n\t"                                     \
        "mbarrier.try_wait.parity.acquire.cta.shared::cta.b64 p, [%1], %2;\n\t" \
        "selp.b32 %0, 1, 0, p;\n\t}" : "=r"(_dn) : "r"(_mb), "r"(_pa) : "memory"); \
    if (!_dn) {                                                               \
        asm volatile("{\n\t.reg .pred P1;\n\t"                                \
            "WL_%=:\n\t"                                                      \
            "mbarrier.try_wait.parity.acquire.cta.shared::cta.b64 P1, [%0], %1, 0x989680;\n\t" \
            "@P1 bra.uni WD_%=;\n\tbra.uni WL_%=;\n\tWD_%=:\n\t}"             \
            :: "r"(_mb), "r"(_pa) : "memory");                                \
    }                                                                         \
} while (0)

// ---- prep W: fold BN scale, transpose, fp16, PRE-SWIZZLED kstep tiles ----
__global__ void prep_W_kernel(const float* __restrict__ W,
                              const float* __restrict__ gamma,
                              const float* __restrict__ mvar) {
    int e = blockIdx.x * 256 + threadIdx.x;
    int n = e & 511, k = e >> 9;
    float s = gamma[n] * rsqrtf(mvar[n] + BN_EPS);
    float v = W[(size_t)k * FDIM + n] * s;
    size_t byte_off = (size_t)(k >> 4) * 16384
                    + TOFF(n, (k & 15) >> 3) + (k & 7) * 2;
    *reinterpret_cast<__half*>(reinterpret_cast<char*>(g_WT) + byte_off) =
        __float2half_rn(v);
}

// ---- main fused kernel ----
__global__ __launch_bounds__(THREADS, 2)
void fused_mma_sparsemax(const float* __restrict__ x,
                         const float* __restrict__ bias,
                         const float* __restrict__ gamma,
                         const float* __restrict__ beta,
                         const float* __restrict__ mmean,
                         const float* __restrict__ mvar,
                         float* __restrict__ out)
{
    extern __shared__ char smem[];
    const uint32_t sb = smem_u32(smem);
    const int tid  = threadIdx.x;
    const int wid  = tid >> 5;             // warp col 0..7 (64 cols each)
    const int lane = tid & 31;
    const int r0   = blockIdx.x * BM;

    float acc[2][8][4];
    #pragma unroll
    for (int i = 0; i < 2; i++)
        #pragma unroll
        for (int j = 0; j < 8; j++)
            #pragma unroll
            for (int q = 0; q < 4; q++) acc[i][j][q] = 0.0f;

    // ---- A conversion role: thread -> (row, 4 consecutive k) of a 32x32 stage
    const int cv_row = tid >> 3;           // 0..31
    const int cv_k   = (tid & 7) * 4;      // 0,4,...,28
    const uint32_t cv_off = (cv_k >> 4) * 1024 +
                            TOFF(cv_row, (cv_k & 15) >> 3) + (cv_k & 7) * 2;
    const float* cv_src = x + (size_t)(r0 + cv_row) * FDIM + cv_k;

    auto cvt_sts = [&](float4 v, int s) {
        char* stg = smem + s * STAGE_BYTES;
        __half2 h01 = __floats2half2_rn(v.x, v.y);
        __half2 h23 = __floats2half2_rn(v.z, v.w);
        *reinterpret_cast<__half2*>(stg + A_O + cv_off)     = h01;
        *reinterpret_cast<__half2*>(stg + A_O + cv_off + 4) = h23;
    };

    // ---- mbarrier init (one per stage) ----
    if (tid == 0) {
        MBARRIER_INIT(sb + MBAR_O + 0,  1);
        MBARRIER_INIT(sb + MBAR_O + 8,  1);
        MBARRIER_INIT(sb + MBAR_O + 16, 1);
    }
    __syncthreads();

    // ---- B DMA: one 32KB bulk copy per stage (pre-swizzled source) ----
    auto issue_B = [&](int t, int s) {      // t = stage index (32 k each)
        MBARRIER_EXPECT_TX(sb + MBAR_O + s * 8, 32768);
        BULK_G2S(sb + s * STAGE_BYTES + B_O,
                 (const char*)g_WT + (size_t)t * 32768,
                 32768, sb + MBAR_O + s * 8);
    };

    // ldmatrix lane addressing
    const int lrow = (lane & 7) + ((lane >> 3) & 1) * 8;
    const int lkc  = (lane >> 4) & 1;
    const uint32_t t_base = TOFF(lrow, lkc);

    // ---- prologue
    float4 a_cur;
    {
        if (tid == 0) { issue_B(0, 0); issue_B(1, 1); }
        float4 a0 = *reinterpret_cast<const float4*>(cv_src);          // stage 0
        cvt_sts(a0, 0);
        a_cur = *reinterpret_cast<const float4*>(cv_src + 32);         // stage 1
    }

    int ph0 = 0, ph1 = 0, ph2 = 0;
    for (int t = 0; t < NSTAGE_IT; t++) {
        const int s = t % 3;
        if (s == 0)      { MBARRIER_WAIT_PARITY(sb + MBAR_O + 0,  ph0); ph0 ^= 1; }
        else if (s == 1) { MBARRIER_WAIT_PARITY(sb + MBAR_O + 8,  ph1); ph1 ^= 1; }
        else             { MBARRIER_WAIT_PARITY(sb + MBAR_O + 16, ph2); ph2 ^= 1; }
        __syncthreads();   // A tile of stage s visible; prior readers of the
                           // stage being overwritten below are done

        if (t + 2 < NSTAGE_IT && tid == 0) issue_B(t + 2, (t + 2) % 3);
        if (t + 1 < NSTAGE_IT) cvt_sts(a_cur, (t + 1) % 3);
        if (t + 2 < NSTAGE_IT)
            a_cur = *reinterpret_cast<const float4*>(cv_src + (t + 2) * 32);

        const uint32_t stg = sb + s * STAGE_BYTES;
        #pragma unroll
        for (int ks = 0; ks < 2; ks++) {
            const uint32_t a_b = stg + A_O + ks * 1024 + t_base;
            const uint32_t b_b = stg + B_O + ks * 16384 + t_base + wid * 2048;

            // hoist ALL LDSM first (independent; one exposed latency)
            uint32_t aH[2][4], bb[4][4];
            #pragma unroll
            for (int mt = 0; mt < 2; mt++)
                LDSM4(aH[mt], a_b + mt * 512);
            #pragma unroll
            for (int ntp = 0; ntp < 4; ntp++)
                LDSM4(bb[ntp], b_b + ntp * 512);
            #pragma unroll
            for (int ntp = 0; ntp < 4; ntp++) {
                #pragma unroll
                for (int mt = 0; mt < 2; mt++) {
                    MMA16816(acc[mt][2 * ntp],     aH[mt], bb[ntp][0], bb[ntp][2]);
                    MMA16816(acc[mt][2 * ntp + 1], aH[mt], bb[ntp][1], bb[ntp][3]);
                }
            }
        }
    }
    __syncthreads();

    // ---- stage accumulators to SMEM with BN shift applied at write
    // (z = acc + shf; same add/order as before -> identical rel_err)
    float* stage = reinterpret_cast<float*>(smem);
    {
        float shfw[8][2];
        #pragma unroll
        for (int nt = 0; nt < 8; nt++) {
            #pragma unroll
            for (int q = 0; q < 2; q++) {
                int f = wid * 64 + nt * 8 + (lane & 3) * 2 + q;
                float s = gamma[f] * rsqrtf(mvar[f] + BN_EPS);
                shfw[nt][q] = fmaf(bias[f] - mmean[f], s, beta[f]);
            }
        }
        #pragma unroll
        for (int mt = 0; mt < 2; mt++) {
            #pragma unroll
            for (int nt = 0; nt < 8; nt++) {
                int row = mt * 16 + (lane >> 2);
                int col = wid * 64 + nt * 8 + (lane & 3) * 2;
                *reinterpret_cast<float2*>(&stage[row * STG_STRIDE + col]) =
                    make_float2(acc[mt][nt][0] + shfw[nt][0],
                                acc[mt][nt][1] + shfw[nt][1]);
                *reinterpret_cast<float2*>(&stage[(row + 8) * STG_STRIDE + col]) =
                    make_float2(acc[mt][nt][2] + shfw[nt][0],
                                acc[mt][nt][3] + shfw[nt][1]);
            }
        }
    }
    __syncthreads();

    // ---- epilogue: 4 rows per warp INTERLEAVED (independent shuffle chains)
    float z[4][16];
    #pragma unroll
    for (int r = 0; r < 4; r++) {
        const int row = wid * 4 + r;
        #pragma unroll
        for (int j = 0; j < 16; j++)
            z[r][j] = stage[row * STG_STRIDE + lane + 32 * j];
    }

    float mx[4];
    #pragma unroll
    for (int r = 0; r < 4; r++) {
        float m = z[r][0];
        #pragma unroll
        for (int j = 1; j < 16; j++) m = fmaxf(m, z[r][j]);
        mx[r] = m;
    }
    #pragma unroll
    for (int off = 16; off > 0; off >>= 1)
        #pragma unroll
        for (int r = 0; r < 4; r++)
            mx[r] = fmaxf(mx[r], __shfl_xor_sync(0xFFFFFFFFu, mx[r], off));

    // joint Michelot: tau_r <- (sum_{z>tau_r} z - 1)/#{z>tau_r}; exit when
    // ALL rows converged (warp-uniform). Converged rows are fixed points.
    float tau[4];
    #pragma unroll
    for (int r = 0; r < 4; r++) tau[r] = mx[r] - 1.0f;

    #pragma unroll 1
    for (int it = 0; it < 24; it++) {
        float S[4], K[4];
        #pragma unroll
        for (int r = 0; r < 4; r++) { S[r] = 0.0f; K[r] = 0.0f; }
        #pragma unroll
        for (int r = 0; r < 4; r++)
            #pragma unroll
            for (int j = 0; j < 16; j++)
                if (z[r][j] > tau[r]) { S[r] += z[r][j]; K[r] += 1.0f; }
        #pragma unroll
        for (int off = 16; off > 0; off >>= 1) {
            #pragma unroll
            for (int r = 0; r < 4; r++) {
                S[r] += __shfl_xor_sync(0xFFFFFFFFu, S[r], off);
                K[r] += __shfl_xor_sync(0xFFFFFFFFu, K[r], off);
            }
        }
        bool done = true;
        #pragma unroll
        for (int r = 0; r < 4; r++) {
            float nt = (S[r] - 1.0f) / K[r];
            done &= !(nt > tau[r] + 1e-7f);
            tau[r] = nt;
        }
        if (done) break;                    // warp-uniform
    }

    #pragma unroll
    for (int r = 0; r < 4; r++) {
        float* orow = out + (size_t)(r0 + wid * 4 + r) * FDIM;
        #pragma unroll
        for (int j = 0; j < 16; j++)
            orow[lane + 32 * j] = fmaxf(z[r][j] - tau[r], 0.0f);
    }
}

extern "C" void kernel_launch(void* const* d_in, const int* in_sizes, int n_in,
                              void* d_out, int out_size)
{
    const float* x     = (const float*)d_in[0];
    const float* W     = (const float*)d_in[1];
    const float* b     = (const float*)d_in[2];
    const float* gamma = (const float*)d_in[3];
    const float* beta  = (const float*)d_in[4];
    const float* mmean = (const float*)d_in[5];
    const float* mvar  = (const float*)d_in[6];
    float* out = (float*)d_out;

    cudaFuncSetAttribute(fused_mma_sparsemax,
                         cudaFuncAttributeMaxDynamicSharedMemorySize, SMEM_BYTES);

    int B = in_sizes[0] / FDIM;                       // 65536
    prep_W_kernel<<<(FDIM * FDIM) / 256, 256>>>(W, gamma, mvar);
    fused_mma_sparsemax<<<B / BM, THREADS, SMEM_BYTES>>>(x, b, gamma, beta, mmean, mvar, out);
}

// round 16
// speedup vs baseline: 1.1100x; 1.1100x over previous
#include <cuda_runtime.h>
#include <cuda_fp16.h>
#include <cstdint>

// Fused sparsemax(BN(x @ W + b)) via warp-level mma.sync.
// R16: B (W) fragments loaded DIRECTLY from gmem into registers — prep kernel
// packs W so one LDG.128 per lane per (kstep,ntp) yields the exact
// ldmatrix.x4 fragment. No B smem, no bulk DMA, no mbarriers: smem traffic
// drops ~2/3 (L1 pipe was 52%). W = 512KB, L2-resident; depth-1 register
// prefetch hides L2 latency. fp16 1-pass (rel_err 7.589e-4, unchanged),
// A via 3-stage smem pipeline, BM=32 / 256 threads / 2 CTAs/SM,
// Michelot sparsemax epilogue (R13 form).

#define FDIM 512
#define BM 32
#define THREADS 256
#define NSTAGE_IT 16                       // 16 iterations x 32 k each
#define BN_EPS 1e-5f
#define STG_STRIDE 520                     // 512 + 8 pad floats

// ---- device scratch (static, no allocation) ----
// g_WB[e*16B], e = t<<10 | wc<<7 | ntp<<5 | lane  (t: kstep 0..31)
// 16B per lane = {m0, m1, m2, m3} fragment words:
//   m0 = {W(k0,n0),  W(k0+1,n0)}    m1 = {W(k0,n0+8), W(k0+1,n0+8)}
//   m2 = {W(k0+8,n0),W(k0+9,n0)}    m3 = {W(k0+8,n0+8),W(k0+9,n0+8)}
// k0 = 16t + 2(lane&3), n0 = wc*64 + ntp*16 + lane/4; BN scale folded in.
__device__ __align__(128) uint4 g_WB[FDIM * FDIM / 8];   // 512 KB

// ---- smem: 3 A stages of 2 KB; epilogue region (66.5 KB) unions them ----
#define A_STAGE_BYTES 2048
#define SMEM_BYTES (BM * STG_STRIDE * 4)   // 66560

// 16B-chunk swizzle inside a [rows][16 fp16] tile (8-row ldmatrix phase
// hits 8 distinct 16B slots of a 128B line).
#define TOFF(r, c) (((((r) << 1) | (c)) ^ (((r) >> 2) & 1)) << 4)

__device__ __forceinline__ uint32_t smem_u32(const void* p) {
    uint32_t a;
    asm("{ .reg .u64 t; cvta.to.shared.u64 t, %1; cvt.u32.u64 %0, t; }" : "=r"(a) : "l"(p));
    return a;
}

#define LDSM4(R, addr)                                                        \
    asm volatile("ldmatrix.sync.aligned.m8n8.x4.shared.b16 {%0,%1,%2,%3}, [%4];" \
                 : "=r"((R)[0]), "=r"((R)[1]), "=r"((R)[2]), "=r"((R)[3])     \
                 : "r"(addr))

#define MMA16816(d, a, b0, b1)                                                \
    asm volatile("mma.sync.aligned.m16n8k16.row.col.f32.f16.f16.f32 "         \
                 "{%0,%1,%2,%3},{%4,%5,%6,%7},{%8,%9},{%0,%1,%2,%3};"         \
                 : "+f"((d)[0]), "+f"((d)[1]), "+f"((d)[2]), "+f"((d)[3])     \
                 : "r"((a)[0]), "r"((a)[1]), "r"((a)[2]), "r"((a)[3]),        \
                   "r"(b0), "r"(b1))

__device__ __forceinline__ uint32_t packh2(__half a, __half b) {
    return (uint32_t)__half_as_ushort(a) | ((uint32_t)__half_as_ushort(b) << 16);
}

// ---- prep: pack W (BN-folded fp16) into per-lane LDG.128 fragments ----
__global__ void prep_WB_kernel(const float* __restrict__ W,
                               const float* __restrict__ gamma,
                               const float* __restrict__ mvar) {
    int e = blockIdx.x * 256 + threadIdx.x;   // 0 .. 32767
    int lane = e & 31;
    int ntp  = (e >> 5) & 3;
    int wc   = (e >> 7) & 7;
    int t    = e >> 10;
    int k0 = t * 16 + 2 * (lane & 3);
    int n0 = wc * 64 + ntp * 16 + (lane >> 2);
    int n1 = n0 + 8;

    float s0 = gamma[n0] * rsqrtf(mvar[n0] + BN_EPS);
    float s1 = gamma[n1] * rsqrtf(mvar[n1] + BN_EPS);

    auto h = [&](int k, int n, float s) {
        return __float2half_rn(W[(size_t)k * FDIM + n] * s);
    };
    uint4 v;
    v.x = packh2(h(k0,     n0, s0), h(k0 + 1, n0, s0));   // m0
    v.y = packh2(h(k0,     n1, s1), h(k0 + 1, n1, s1));   // m1
    v.z = packh2(h(k0 + 8, n0, s0), h(k0 + 9, n0, s0));   // m2
    v.w = packh2(h(k0 + 8, n1, s1), h(k0 + 9, n1, s1));   // m3
    g_WB[e] = v;
}

// ---- main fused kernel ----
__global__ __launch_bounds__(THREADS, 2)
void fused_mma_sparsemax(const float* __restrict__ x,
                         const float* __restrict__ bias,
                         const float* __restrict__ gamma,
                         const float* __restrict__ beta,
                         const float* __restrict__ mmean,
                         const float* __restrict__ mvar,
                         float* __restrict__ out)
{
    extern __shared__ char smem[];
    const uint32_t sb = smem_u32(smem);
    const int tid  = threadIdx.x;
    const int wid  = tid >> 5;             // warp col 0..7 (64 cols each)
    const int lane = tid & 31;
    const int r0   = blockIdx.x * BM;

    float acc[2][8][4];
    #pragma unroll
    for (int i = 0; i < 2; i++)
        #pragma unroll
        for (int j = 0; j < 8; j++)
            #pragma unroll
            for (int q = 0; q < 4; q++) acc[i][j][q] = 0.0f;

    // ---- A conversion role: thread -> (row, 4 consecutive k) of a 32x32 stage
    const int cv_row = tid >> 3;           // 0..31
    const int cv_k   = (tid & 7) * 4;      // 0,4,...,28
    const uint32_t cv_off = (cv_k >> 4) * 1024 +
                            TOFF(cv_row, (cv_k & 15) >> 3) + (cv_k & 7) * 2;
    const float* cv_src = x + (size_t)(r0 + cv_row) * FDIM + cv_k;

    auto cvt_sts = [&](float4 v, int s) {
        char* stg = smem + s * A_STAGE_BYTES;
        __half2 h01 = __floats2half2_rn(v.x, v.y);
        __half2 h23 = __floats2half2_rn(v.z, v.w);
        *reinterpret_cast<__half2*>(stg + cv_off)     = h01;
        *reinterpret_cast<__half2*>(stg + cv_off + 4) = h23;
    };

    // ---- B fragment source (gmem, L2-resident): per-warp base ----
    const uint4* b_base = g_WB + (size_t)wid * 4 * 32 + lane;   // + kk*1024 + ntp*32

    uint32_t bb[2][4][4];                  // ping-pong fragment buffers
    auto load_B = [&](int kk, uint32_t d[4][4]) {
        #pragma unroll
        for (int ntp = 0; ntp < 4; ntp++) {
            uint4 v = __ldg(b_base + (size_t)kk * 1024 + ntp * 32);
            d[ntp][0] = v.x; d[ntp][1] = v.y; d[ntp][2] = v.z; d[ntp][3] = v.w;
        }
    };

    // ldmatrix lane addressing (A tiles)
    const int lrow = (lane & 7) + ((lane >> 3) & 1) * 8;
    const int lkc  = (lane >> 4) & 1;
    const uint32_t t_base = TOFF(lrow, lkc);

    // ---- prologue: A stage 0 + B fragments for kstep 0
    float4 a_cur;
    {
        float4 a0 = *reinterpret_cast<const float4*>(cv_src);          // stage 0
        cvt_sts(a0, 0);
        a_cur = *reinterpret_cast<const float4*>(cv_src + 32);         // stage 1
        load_B(0, bb[0]);
    }
    __syncthreads();

    for (int t = 0; t < NSTAGE_IT; t++) {
        // write A for stage t+1 into buffer (t+1)%3; prefetch stage t+2 LDG
        if (t + 1 < NSTAGE_IT) cvt_sts(a_cur, (t + 1) % 3);
        if (t + 2 < NSTAGE_IT)
            a_cur = *reinterpret_cast<const float4*>(cv_src + (t + 2) * 32);

        const uint32_t stg = sb + (t % 3) * A_STAGE_BYTES;
        #pragma unroll
        for (int ks = 0; ks < 2; ks++) {
            const int kk = 2 * t + ks;
            const uint32_t a_b = stg + ks * 1024 + t_base;

            // prefetch next kstep's B fragments (depth 1)
            if (kk + 1 < 32) load_B(kk + 1, bb[(kk + 1) & 1]);

            uint32_t aH[2][4];
            #pragma unroll
            for (int mt = 0; mt < 2; mt++)
                LDSM4(aH[mt], a_b + mt * 512);

            uint32_t (*bc)[4] = bb[kk & 1];
            #pragma unroll
            for (int ntp = 0; ntp < 4; ntp++) {
                #pragma unroll
                for (int mt = 0; mt < 2; mt++) {
                    MMA16816(acc[mt][2 * ntp],     aH[mt], bc[ntp][0], bc[ntp][2]);
                    MMA16816(acc[mt][2 * ntp + 1], aH[mt], bc[ntp][1], bc[ntp][3]);
                }
            }
        }
        __syncthreads();   // A stage t consumed; (t+1)%3 writes visible next iter
    }

    // ---- stage accumulators to SMEM (epilogue region unions A stages)
    float* stage = reinterpret_cast<float*>(smem);
    #pragma unroll
    for (int mt = 0; mt < 2; mt++) {
        #pragma unroll
        for (int nt = 0; nt < 8; nt++) {
            int row = mt * 16 + (lane >> 2);
            int col = wid * 64 + nt * 8 + (lane & 3) * 2;
            *reinterpret_cast<float2*>(&stage[row * STG_STRIDE + col]) =
                make_float2(acc[mt][nt][0], acc[mt][nt][1]);
            *reinterpret_cast<float2*>(&stage[(row + 8) * STG_STRIDE + col]) =
                make_float2(acc[mt][nt][2], acc[mt][nt][3]);
        }
    }
    __syncthreads();

    // ---- epilogue: BN shift + Michelot sparsemax, 4 rows/warp, 16 cols/lane
    float shf[16];
    #pragma unroll
    for (int j = 0; j < 16; j++) {
        int f = lane + 32 * j;
        float s = gamma[f] * rsqrtf(mvar[f] + BN_EPS);
        shf[j] = fmaf(bias[f] - mmean[f], s, beta[f]);
    }

    #pragma unroll 1
    for (int i = 0; i < 4; i++) {
        const int row = wid * 4 + i;
        float z[16];
        #pragma unroll
        for (int j = 0; j < 16; j++)
            z[j] = stage[row * STG_STRIDE + lane + 32 * j] + shf[j];

        float m = -1e30f;
        #pragma unroll
        for (int j = 0; j < 16; j++) m = fmaxf(m, z[j]);
        #pragma unroll
        for (int off = 16; off > 0; off >>= 1)
            m = fmaxf(m, __shfl_xor_sync(0xFFFFFFFFu, m, off));

        // Michelot fixed point: tau <- (sum_{z>tau} z - 1)/#{z>tau}
        float tau = m - 1.0f;
        #pragma unroll 1
        for (int it = 0; it < 24; it++) {
            float S = 0.0f, K = 0.0f;
            #pragma unroll
            for (int j = 0; j < 16; j++) {
                if (z[j] > tau) { S += z[j]; K += 1.0f; }
            }
            #pragma unroll
            for (int off = 16; off > 0; off >>= 1) {
                S += __shfl_xor_sync(0xFFFFFFFFu, S, off);
                K += __shfl_xor_sync(0xFFFFFFFFu, K, off);
            }
            float nt = (S - 1.0f) / K;
            bool done = !(nt > tau + 1e-7f);  // warp-uniform
            tau = nt;
            if (done) break;
        }

        float* orow = out + (size_t)(r0 + row) * FDIM;
        #pragma unroll
        for (int j = 0; j < 16; j++)
            orow[lane + 32 * j] = fmaxf(z[j] - tau, 0.0f);
    }
}

extern "C" void kernel_launch(void* const* d_in, const int* in_sizes, int n_in,
                              void* d_out, int out_size)
{
    const float* x     = (const float*)d_in[0];
    const float* W     = (const float*)d_in[1];
    const float* b     = (const float*)d_in[2];
    const float* gamma = (const float*)d_in[3];
    const float* beta  = (const float*)d_in[4];
    const float* mmean = (const float*)d_in[5];
    const float* mvar  = (const float*)d_in[6];
    float* out = (float*)d_out;

    cudaFuncSetAttribute(fused_mma_sparsemax,
                         cudaFuncAttributeMaxDynamicSharedMemorySize, SMEM_BYTES);

    int B = in_sizes[0] / FDIM;                       // 65536
    prep_WB_kernel<<<128, 256>>>(W, gamma, mvar);
    fused_mma_sparsemax<<<B / BM, THREADS, SMEM_BYTES>>>(x, b, gamma, beta, mmean, mvar, out);
}